// round 5
// baseline (speedup 1.0000x reference)
#include <cuda_runtime.h>
#include <cstdint>

#define NPTS   8192
#define NB     4
#define NC     1024
#define KNN    32
#define DFEAT  13
#define NROWS  (NB*NC*KNN)          // 131072
#define CENT_FLOATS (NB*NC*3)       // 12288

static __device__ float  g_x2[NB*NPTS];
static __device__ float  g_grouped[(size_t)NROWS*16];
static __device__ float  g_y0[(size_t)NROWS*64];
static __device__ float  g_y1[(size_t)NROWS*64];
static __device__ float  g_y2[(size_t)NROWS*128];
// stats: [0:64) s0 [64:128) ss0 [128:192) s1 [192:256) ss1 [256:384) s2 [384:512) ss2
static __device__ double g_stats[512];

__device__ __forceinline__ float f_inf() { return __int_as_float(0x7f800000); }

// ---------------- threefry2x32 (matches jax), fully unrolled ----------------
__device__ __forceinline__ uint32_t rotl32(uint32_t x, int d) { return (x << d) | (x >> (32 - d)); }

__device__ __forceinline__ void threefry2x32(uint32_t k0, uint32_t k1, uint32_t c0, uint32_t c1,
                                             uint32_t& o0, uint32_t& o1) {
    uint32_t ks0 = k0, ks1 = k1, ks2 = k0 ^ k1 ^ 0x1BD11BDAu;
    uint32_t x0 = c0 + ks0, x1 = c1 + ks1;
#define TF_R(r) { x0 += x1; x1 = rotl32(x1, r); x1 ^= x0; }
#define TF_A TF_R(13) TF_R(15) TF_R(26) TF_R(6)
#define TF_B TF_R(17) TF_R(29) TF_R(16) TF_R(24)
    TF_A; x0 += ks1; x1 += ks2 + 1u;
    TF_B; x0 += ks2; x1 += ks0 + 2u;
    TF_A; x0 += ks0; x1 += ks1 + 3u;
    TF_B; x0 += ks1; x1 += ks2 + 4u;
    TF_A; x0 += ks2; x1 += ks0 + 5u;
#undef TF_A
#undef TF_B
#undef TF_R
    o0 = x0; o1 = x1;
}

// ---------------- zero stats ----------------
__global__ void zero_stats_kernel() {
    int i = threadIdx.x;
    if (i < 512) g_stats[i] = 0.0;
}

// ---------------- FPS: one block per batch, 512 threads x 16 points ----------------
// Tracks squared distances; argmax is resolved in *sqrt domain* (matching
// jnp.linalg.norm + argmax semantics incl. first-index ties) via a two-phase
// reduce: (A) plain d2 max, (B) rescan values within 8 ulps of d2max, take
// exact (sqrt_bits, first-index) winner with correctly-rounded sqrt.
__global__ __launch_bounds__(512, 1) void fps_kernel(const float* __restrict__ coords,
                                                     float* __restrict__ out_cent) {
    const int b = blockIdx.x;
    const float* cb = coords + (size_t)b * NPTS * 3;
    const int tid = threadIdx.x;
    const int wid = tid >> 5, lane = tid & 31;

    float px[16], py[16], pz[16], dist[16];
#pragma unroll
    for (int t = 0; t < 16; t++) {
        int p = tid + t * 512;
        px[t] = cb[3 * p]; py[t] = cb[3 * p + 1]; pz[t] = cb[3 * p + 2];
        dist[t] = f_inf();
        // x2 = sum(coords*coords): plain mul+add (no fma) to mimic XLA reduce
        g_x2[b * NPTS + p] = __fadd_rn(__fadd_rn(__fmul_rn(px[t], px[t]), __fmul_rn(py[t], py[t])),
                                       __fmul_rn(pz[t], pz[t]));
    }

    __shared__ float scx, scy, scz;
    __shared__ int sfar;
    __shared__ float s_d2max;
    __shared__ float swv[16];
    __shared__ unsigned long long swk[16];

    if (tid == 0) {
        // jax_threefry_partitionable=True (modern jax default) derivations:
        //   split(key(42), 2) [foldlike]: key_i = threefry2x32((0,42), (0, i)), both words.
        //   k2 = keys[1] = threefry((0,42), (0,1)).
        //   random_bits(k2, 32, (4,)) [partitionable]: per element b,
        //     (o0,o1) = threefry(k2, (0,b)); bits = o0 ^ o1.
        //   randint span=8192 -> multiplier=0 -> far0 = bits & 8191.
        uint32_t k2a, k2b;
        threefry2x32(0u, 42u, 0u, 1u, k2a, k2b);
        uint32_t o0, o1;
        threefry2x32(k2a, k2b, 0u, (uint32_t)b, o0, o1);
        sfar = (int)((o0 ^ o1) & 8191u);
    }
    __syncthreads();
    int f = sfar;

    for (int it = 0; it < NC; ++it) {
        if (tid == 0) {
            float x = cb[3 * f], y = cb[3 * f + 1], z = cb[3 * f + 2];
            scx = x; scy = y; scz = z;
            float* oc = out_cent + ((size_t)b * NC + it) * 3;
            oc[0] = x; oc[1] = y; oc[2] = z;
        }
        __syncthreads();
        float fx = scx, fy = scy, fz = scz;

        // Phase A: update running min d2; find plain d2 max (no index).
        float mv = -1.0f;
#pragma unroll
        for (int t = 0; t < 16; t++) {
            float dx = px[t] - fx, dy = py[t] - fy, dz = pz[t] - fz;
            float d2 = __fadd_rn(__fadd_rn(__fmul_rn(dx, dx), __fmul_rn(dy, dy)),
                                 __fmul_rn(dz, dz));
            float nd = fminf(dist[t], d2);
            dist[t] = nd;
            mv = fmaxf(mv, nd);
        }
#pragma unroll
        for (int off = 16; off; off >>= 1)
            mv = fmaxf(mv, __shfl_xor_sync(0xffffffffu, mv, off));
        if (lane == 0) swv[wid] = mv;
        __syncthreads();
        if (tid == 0) {
            float m = swv[0];
#pragma unroll
            for (int w = 1; w < 16; w++) m = fmaxf(m, swv[w]);
            s_d2max = m;
        }
        __syncthreads();

        // Phase B: candidates within 8 ulps of d2max -> exact sqrt-domain winner.
        uint32_t mb = __float_as_uint(s_d2max);
        uint32_t thr = (mb >= 8u) ? (mb - 8u) : 0u;
        unsigned long long key = 0ull;
#pragma unroll
        for (int t = 0; t < 16; t++) {
            if (__float_as_uint(dist[t]) >= thr) {
                float s = __fsqrt_rn(dist[t]);
                unsigned long long k = ((unsigned long long)__float_as_uint(s) << 32)
                                     | (uint32_t)(0x7fffffff - (tid + t * 512));
                if (k > key) key = k;
            }
        }
#pragma unroll
        for (int off = 16; off; off >>= 1) {
            unsigned long long ok = __shfl_xor_sync(0xffffffffu, key, off);
            if (ok > key) key = ok;
        }
        if (lane == 0) swk[wid] = key;
        __syncthreads();
        if (tid == 0) {
            unsigned long long m = swk[0];
#pragma unroll
            for (int w = 1; w < 16; w++) if (swk[w] > m) m = swk[w];
            sfar = 0x7fffffff - (int)(uint32_t)(m & 0xffffffffull);
        }
        __syncthreads();
        f = sfar;
    }
}

// ---------------- grouping: one block per (b,c) ----------------
__global__ __launch_bounds__(256) void group_kernel(const float* __restrict__ coords,
                                                    const float* __restrict__ features,
                                                    const float* __restrict__ cent,
                                                    float* __restrict__ grouped) {
    const int bc = blockIdx.x;
    const int b = bc >> 10;
    const int tid = threadIdx.x;
    const float* cb = coords + (size_t)b * NPTS * 3;
    const float* fb = features + (size_t)b * NPTS * DFEAT;
    const float* x2b = g_x2 + b * NPTS;

    const float cx = cent[3 * bc], cy = cent[3 * bc + 1], cz = cent[3 * bc + 2];
    const float c2 = __fadd_rn(__fadd_rn(__fmul_rn(cx, cx), __fmul_rn(cy, cy)), __fmul_rn(cz, cz));
    const float r2 = 0.04f;   // f32(0.2*0.2 computed in f64) = 0x3D23D70A

    __shared__ float sval[1024];
    __shared__ int sidx[1024];
    __shared__ int scnt;
    __shared__ unsigned long long swmin[8];
    __shared__ unsigned long long sbest;
    __shared__ int schosen[KNN];

    if (tid == 0) scnt = 0;
    __syncthreads();

    for (int n = tid; n < NPTS; n += 256) {
        float x = cb[3 * n], y = cb[3 * n + 1], z = cb[3 * n + 2];
        float dot = __fmaf_rn(cz, z, __fmaf_rn(cy, y, __fmul_rn(cx, x)));
        float d = __fadd_rn(__fmaf_rn(-2.0f, dot, c2), x2b[n]);
        if (d <= r2) {
            int p = atomicAdd(&scnt, 1);
            if (p < 1024) { sval[p] = d; sidx[p] = n; }
        }
    }
    __syncthreads();
    const int M = min(scnt, 1024);
    const int nsel = min(M, KNN);
    const int wid = tid >> 5, lane = tid & 31;

    for (int round = 0; round < nsel; round++) {
        unsigned long long bk = 0xFFFFFFFFFFFFFFFFull;
        for (int j = tid; j < M; j += 256) {
            unsigned u = __float_as_uint(sval[j]);
            u = (u & 0x80000000u) ? ~u : (u | 0x80000000u);  // orderable
            unsigned long long k = ((unsigned long long)u << 32) | (unsigned)sidx[j];
            if (k < bk) bk = k;
        }
#pragma unroll
        for (int off = 16; off; off >>= 1) {
            unsigned long long ok = __shfl_down_sync(0xffffffffu, bk, off);
            if (ok < bk) bk = ok;
        }
        if (lane == 0) swmin[wid] = bk;
        __syncthreads();
        if (tid == 0) {
            unsigned long long m = swmin[0];
            for (int w = 1; w < 8; w++) if (swmin[w] < m) m = swmin[w];
            sbest = m;
        }
        __syncthreads();
        int n = (int)(unsigned)(sbest & 0xFFFFFFFFull);
        if (tid == 0) schosen[round] = n;
        for (int j = tid; j < M; j += 256)
            if (sidx[j] == n) sval[j] = f_inf();
        __syncthreads();
    }

    if (nsel < KNN && tid == 0) {  // pad with lowest-index out-of-radius points (top_k on inf ties)
        int pos = nsel;
        for (int n = 0; n < NPTS && pos < KNN; n++) {
            float x = cb[3 * n], y = cb[3 * n + 1], z = cb[3 * n + 2];
            float dot = __fmaf_rn(cz, z, __fmaf_rn(cy, y, __fmul_rn(cx, x)));
            float d = __fadd_rn(__fmaf_rn(-2.0f, dot, c2), x2b[n]);
            if (!(d <= r2)) schosen[pos++] = n;
        }
    }
    __syncthreads();

    for (int t = tid; t < KNN * 16; t += 256) {
        int k = t >> 4, fc = t & 15;
        int n = schosen[k];
        float v;
        if (fc < 3) {
            float cen = (fc == 0) ? cx : ((fc == 1) ? cy : cz);
            v = cb[3 * n + fc] - cen;
        } else {
            v = fb[DFEAT * n + fc - 3];
        }
        grouped[((size_t)bc * KNN + k) * 16 + fc] = v;
    }
}

// ---------------- GEMM: shared-memory tiled ----------------
template <int FIN, int FOUT, int SOFF, bool NORM>
__global__ __launch_bounds__(256) void gemm_kernel(const float* __restrict__ X,
                                                   const float* __restrict__ W,
                                                   const float* __restrict__ bias,
                                                   const float* __restrict__ gam,
                                                   const float* __restrict__ bet,
                                                   float* __restrict__ Y) {
    constexpr int ROWS = 32;
    constexpr int FPG = FOUT / 8;       // outputs per thread
    constexpr int WP = FIN + 1;         // padded weight row to avoid bank conflicts

    __shared__ float sW[FOUT * WP];
    __shared__ float sB[FOUT];
    __shared__ float sA[FIN], sC[FIN];
    __shared__ float sX[ROWS * FIN];

    const int tid = threadIdx.x;

    for (int i = tid; i < FOUT * FIN; i += 256) sW[(i / FIN) * WP + (i % FIN)] = W[i];
    if (tid < FOUT) sB[tid] = bias[tid];
    if (NORM && tid < FIN) {
        double mu = g_stats[SOFF + tid] / (double)NROWS;
        double var = g_stats[SOFF + FIN + tid] / (double)NROWS - mu * mu;
        float a = (float)(1.0 / sqrt(var + 1e-5)) * gam[tid];
        sA[tid] = a;
        sC[tid] = bet[tid] - (float)mu * a;
    }
    __syncthreads();

    const float* xblk = X + (size_t)blockIdx.x * ROWS * FIN;
    for (int i = tid; i < ROWS * FIN; i += 256) {
        float v = xblk[i];
        if (NORM) {
            int ch = i % FIN;
            v = fmaxf(fmaf(v, sA[ch], sC[ch]), 0.0f);
        }
        sX[i] = v;
    }
    __syncthreads();

    const int row = tid >> 3;           // 0..31
    const int og = tid & 7;             // 0..7
    const float* xr = &sX[row * FIN];

    float acc[FPG];
#pragma unroll
    for (int j = 0; j < FPG; j++) acc[j] = sB[og * FPG + j];
#pragma unroll
    for (int i = 0; i < FIN; i++) {
        float xv = xr[i];
#pragma unroll
        for (int j = 0; j < FPG; j++)
            acc[j] = fmaf(xv, sW[(og * FPG + j) * WP + i], acc[j]);
    }
    float* yr = Y + ((size_t)blockIdx.x * ROWS + row) * FOUT + og * FPG;
#pragma unroll
    for (int j = 0; j < FPG; j++) yr[j] = acc[j];
}

// ---------------- per-channel sum / sumsq reduction ----------------
template <int F, int SOFF>
__global__ __launch_bounds__(256) void stats_kernel(const float* __restrict__ y) {
    constexpr int GROUPS = 256 / F;     // 4 for F=64, 2 for F=128
    const int g = threadIdx.x / F, ch = threadIdx.x % F;
    const int base = blockIdx.x * 512;  // 512 rows per block, 256 blocks
    float s = 0.0f, ss = 0.0f;
    for (int r = base + g; r < base + 512; r += GROUPS) {
        float v = y[(size_t)r * F + ch];
        s += v;
        ss = fmaf(v, v, ss);
    }
    __shared__ float sh[256], sh2[256];
    sh[threadIdx.x] = s; sh2[threadIdx.x] = ss;
    __syncthreads();
    if (g == 0) {
#pragma unroll
        for (int gg = 1; gg < GROUPS; gg++) { s += sh[gg * F + ch]; ss += sh2[gg * F + ch]; }
        atomicAdd(&g_stats[SOFF + ch], (double)s);
        atomicAdd(&g_stats[SOFF + F + ch], (double)ss);
    }
}

// ---------------- BN+ReLU+maxpool over K ----------------
__global__ __launch_bounds__(128) void pool_kernel(const float* __restrict__ gam,
                                                   const float* __restrict__ bet,
                                                   float* __restrict__ out) {
    const int bc = blockIdx.x;
    const int o = threadIdx.x;  // 128 channels
    double mu = g_stats[256 + o] / (double)NROWS;
    double var = g_stats[384 + o] / (double)NROWS - mu * mu;
    float a = (float)(1.0 / sqrt(var + 1e-5)) * gam[o];
    float c = bet[o] - (float)mu * a;
    float m = 0.0f;  // relu >= 0
#pragma unroll
    for (int k = 0; k < KNN; k++) {
        float v = g_y2[((size_t)bc * KNN + k) * 128 + o];
        v = fmaxf(fmaf(v, a, c), 0.0f);
        m = fmaxf(m, v);
    }
    out[CENT_FLOATS + (size_t)bc * 128 + o] = m;
}

extern "C" void kernel_launch(void* const* d_in, const int* in_sizes, int n_in,
                              void* d_out, int out_size) {
    // ---- resolve inputs by element count (order-agnostic) ----
    int i_coords = -1, i_features = -1, i_w0 = -1, i_w1 = -1, i_w2 = -1;
    int idx64[6], n64 = 0;
    int idx128[3], n128 = 0;
    for (int i = 0; i < n_in; i++) {
        int s = in_sizes[i];
        if (s == 98304) i_coords = i;
        else if (s == 425984) i_features = i;
        else if (s == 1024) i_w0 = i;
        else if (s == 4096) i_w1 = i;
        else if (s == 8192) i_w2 = i;
        else if (s == 64 && n64 < 6) idx64[n64++] = i;
        else if (s == 128 && n128 < 3) idx128[n128++] = i;
    }

    int i_b0, i_g0, i_be0, i_b1, i_g1, i_be1, i_b2, i_g2, i_be2;
    if (i_coords == 0) {
        // signature order: coords, features, w0, b0, g0, be0, w1, b1, g1, be1, w2, b2, g2, be2
        i_b0 = idx64[0]; i_g0 = idx64[1]; i_be0 = idx64[2];
        i_b1 = idx64[3]; i_g1 = idx64[4]; i_be1 = idx64[5];
        i_b2 = idx128[0]; i_g2 = idx128[1]; i_be2 = idx128[2];
    } else {
        // alphabetical: b0,b1,b2,be0,be1,be2,coords,features,g0,g1,g2,w0,w1,w2
        i_b0 = idx64[0]; i_b1 = idx64[1]; i_be0 = idx64[2];
        i_be1 = idx64[3]; i_g0 = idx64[4]; i_g1 = idx64[5];
        i_b2 = idx128[0]; i_be2 = idx128[1]; i_g2 = idx128[2];
    }

    const float* coords   = (const float*)d_in[i_coords];
    const float* features = (const float*)d_in[i_features];
    const float* w0 = (const float*)d_in[i_w0];
    const float* b0 = (const float*)d_in[i_b0];
    const float* g0 = (const float*)d_in[i_g0];
    const float* be0 = (const float*)d_in[i_be0];
    const float* w1 = (const float*)d_in[i_w1];
    const float* b1 = (const float*)d_in[i_b1];
    const float* g1 = (const float*)d_in[i_g1];
    const float* be1 = (const float*)d_in[i_be1];
    const float* w2 = (const float*)d_in[i_w2];
    const float* b2 = (const float*)d_in[i_b2];
    const float* g2 = (const float*)d_in[i_g2];
    const float* be2 = (const float*)d_in[i_be2];
    float* out = (float*)d_out;

    (void)out_size;

    float* y0; float* y1; float* y2; float* gr;
    cudaGetSymbolAddress((void**)&gr, g_grouped);
    cudaGetSymbolAddress((void**)&y0, g_y0);
    cudaGetSymbolAddress((void**)&y1, g_y1);
    cudaGetSymbolAddress((void**)&y2, g_y2);

    zero_stats_kernel<<<1, 512>>>();
    fps_kernel<<<NB, 512>>>(coords, out);                       // writes cent + g_x2
    group_kernel<<<NB * NC, 256>>>(coords, features, out, gr);

    gemm_kernel<16, 64, 0, false><<<NROWS / 32, 256>>>(gr, w0, b0, nullptr, nullptr, y0);
    stats_kernel<64, 0><<<256, 256>>>(y0);
    gemm_kernel<64, 64, 0, true><<<NROWS / 32, 256>>>(y0, w1, b1, g0, be0, y1);
    stats_kernel<64, 128><<<256, 256>>>(y1);
    gemm_kernel<64, 128, 128, true><<<NROWS / 32, 256>>>(y1, w2, b2, g1, be1, y2);
    stats_kernel<128, 256><<<256, 256>>>(y2);
    pool_kernel<<<NB * NC, 128>>>(g2, be2, out);
}

// round 7
// speedup vs baseline: 1.1838x; 1.1838x over previous
#include <cuda_runtime.h>
#include <cstdint>

#define NPTS   8192
#define NB     4
#define NC     1024
#define KNN    32
#define DFEAT  13
#define NROWS  (NB*NC*KNN)          // 131072
#define CENT_FLOATS (NB*NC*3)       // 12288

static __device__ float  g_x2[NB*NPTS];
static __device__ float  g_grouped[(size_t)NROWS*16];
static __device__ float  g_y0[(size_t)NROWS*64];
static __device__ float  g_y1[(size_t)NROWS*64];
static __device__ float  g_y2[(size_t)NROWS*128];
// stats: [0:64) s0 [64:128) ss0 [128:192) s1 [192:256) ss1 [256:384) s2 [384:512) ss2
static __device__ double g_stats[512];

__device__ __forceinline__ float f_inf() { return __int_as_float(0x7f800000); }

// packed f32x2 ops (per-lane IEEE rn, identical to scalar __fadd_rn/__fmul_rn)
#define MUL_F32X2(out, a, b) asm("mul.rn.f32x2 %0, %1, %2;" : "=l"(out) : "l"(a), "l"(b))
#define ADD_F32X2(out, a, b) asm("add.rn.f32x2 %0, %1, %2;" : "=l"(out) : "l"(a), "l"(b))
#define PACK_F32X2(out, lo, hi) asm("mov.b64 %0, {%1, %2};" : "=l"(out) : "r"(lo), "r"(hi))
#define UNPACK_F32X2(lo, hi, in) asm("mov.b64 {%0, %1}, %2;" : "=r"(lo), "=r"(hi) : "l"(in))

// ---------------- threefry2x32 (jax partitionable mode) ----------------
__device__ __forceinline__ uint32_t rotl32(uint32_t x, int d) { return (x << d) | (x >> (32 - d)); }

__device__ __forceinline__ void threefry2x32(uint32_t k0, uint32_t k1, uint32_t c0, uint32_t c1,
                                             uint32_t& o0, uint32_t& o1) {
    uint32_t ks0 = k0, ks1 = k1, ks2 = k0 ^ k1 ^ 0x1BD11BDAu;
    uint32_t x0 = c0 + ks0, x1 = c1 + ks1;
#define TF_R(r) { x0 += x1; x1 = rotl32(x1, r); x1 ^= x0; }
#define TF_A TF_R(13) TF_R(15) TF_R(26) TF_R(6)
#define TF_B TF_R(17) TF_R(29) TF_R(16) TF_R(24)
    TF_A; x0 += ks1; x1 += ks2 + 1u;
    TF_B; x0 += ks2; x1 += ks0 + 2u;
    TF_A; x0 += ks0; x1 += ks1 + 3u;
    TF_B; x0 += ks1; x1 += ks2 + 4u;
    TF_A; x0 += ks2; x1 += ks0 + 5u;
#undef TF_A
#undef TF_B
#undef TF_R
    o0 = x0; o1 = x1;
}

__global__ void zero_stats_kernel() {
    int i = threadIdx.x;
    if (i < 512) g_stats[i] = 0.0;
}

// ---------------- FPS: one block per batch, 512 threads x 16 points ----------------
// d2 computed with packed f32x2 (bit-exact vs scalar rn ops / XLA). argmax in
// sqrt domain (jnp.linalg.norm + argmax first-index ties): phase A = plain d2
// max via REDUX; phase B = sqrt only candidates within 8 ulps of d2max.
__global__ __launch_bounds__(512, 1) void fps_kernel(const float* __restrict__ coords,
                                                     float* __restrict__ out_cent) {
    const int b = blockIdx.x;
    const float* cb = coords + (size_t)b * NPTS * 3;
    const int tid = threadIdx.x;
    const int wid = tid >> 5, lane = tid & 31;

    unsigned long long pxp[8], pyp[8], pzp[8];
    float dist[16];
#pragma unroll
    for (int t = 0; t < 16; t++) {
        int p = tid + t * 512;
        float x = cb[3 * p], y = cb[3 * p + 1], z = cb[3 * p + 2];
        dist[t] = f_inf();
        g_x2[b * NPTS + p] = __fadd_rn(__fadd_rn(__fmul_rn(x, x), __fmul_rn(y, y)),
                                       __fmul_rn(z, z));
    }
    // pack pairs (L1-hot reload): pair m = points tid+2m*512, tid+(2m+1)*512
#pragma unroll
    for (int m = 0; m < 8; m++) {
        int p0 = tid + (2 * m) * 512, p1 = tid + (2 * m + 1) * 512;
        PACK_F32X2(pxp[m], __float_as_uint(cb[3 * p0]),     __float_as_uint(cb[3 * p1]));
        PACK_F32X2(pyp[m], __float_as_uint(cb[3 * p0 + 1]), __float_as_uint(cb[3 * p1 + 1]));
        PACK_F32X2(pzp[m], __float_as_uint(cb[3 * p0 + 2]), __float_as_uint(cb[3 * p1 + 2]));
    }

    __shared__ float scx, scy, scz;
    __shared__ uint32_t swv[16];
    __shared__ unsigned long long swk[16];

    int f = 0;
    if (tid == 0) {
        // partitionable: k2 = threefry((0,42),(0,1)); bits_b = o0^o1 of threefry(k2,(0,b))
        uint32_t k2a, k2b, o0, o1;
        threefry2x32(0u, 42u, 0u, 1u, k2a, k2b);
        threefry2x32(k2a, k2b, 0u, (uint32_t)b, o0, o1);
        f = (int)((o0 ^ o1) & 8191u);
    }

    for (int it = 0; it < NC; ++it) {
        if (tid == 0) {
            float x = cb[3 * f], y = cb[3 * f + 1], z = cb[3 * f + 2];
            scx = x; scy = y; scz = z;
            float* oc = out_cent + ((size_t)b * NC + it) * 3;
            oc[0] = x; oc[1] = y; oc[2] = z;
        }
        __syncthreads();                       // bar 1
        float fx = scx, fy = scy, fz = scz;
        unsigned long long nfx, nfy, nfz;
        {
            uint32_t nx = __float_as_uint(-fx), ny = __float_as_uint(-fy), nz = __float_as_uint(-fz);
            PACK_F32X2(nfx, nx, nx); PACK_F32X2(nfy, ny, ny); PACK_F32X2(nfz, nz, nz);
        }

        // Phase A: packed d2, scalar min-update, running max
        float mv = -1.0f;
#pragma unroll
        for (int m = 0; m < 8; m++) {
            unsigned long long dx, dy, dz, xx, yy, zz, s1, d2p;
            ADD_F32X2(dx, pxp[m], nfx);
            ADD_F32X2(dy, pyp[m], nfy);
            ADD_F32X2(dz, pzp[m], nfz);
            MUL_F32X2(xx, dx, dx);
            MUL_F32X2(yy, dy, dy);
            MUL_F32X2(zz, dz, dz);
            ADD_F32X2(s1, xx, yy);
            ADD_F32X2(d2p, s1, zz);
            uint32_t lo, hi;
            UNPACK_F32X2(lo, hi, d2p);
            float a = __uint_as_float(lo), c = __uint_as_float(hi);
            dist[2 * m]     = fminf(dist[2 * m], a);
            dist[2 * m + 1] = fminf(dist[2 * m + 1], c);
            mv = fmaxf(mv, dist[2 * m]);
            mv = fmaxf(mv, dist[2 * m + 1]);
        }
        uint32_t wmv = __reduce_max_sync(0xffffffffu, __float_as_uint(mv));  // d2>=0: bits monotone
        if (lane == 0) swv[wid] = wmv;
        __syncthreads();                       // bar 2
        uint32_t u = (lane < 16) ? swv[lane] : 0u;
        uint32_t dmb = __reduce_max_sync(0xffffffffu, u);   // every warp gets d2max bits
        uint32_t thr = (dmb >= 8u) ? (dmb - 8u) : 0u;

        // Phase B: sqrt only near-max candidates; exact (sqrt_bits, first-idx) winner
        uint32_t best = 0u; uint32_t bidx = 0x7fffffffu;
#pragma unroll
        for (int t = 0; t < 16; t++) {
            if (__float_as_uint(dist[t]) >= thr) {
                uint32_t sb = __float_as_uint(__fsqrt_rn(dist[t]));
                if (sb > best) { best = sb; bidx = (uint32_t)(tid + t * 512); }
            }
        }
        uint32_t wmax = __reduce_max_sync(0xffffffffu, best);
        uint32_t cand = (best == wmax) ? bidx : 0xffffffffu;
        uint32_t widx = __reduce_min_sync(0xffffffffu, cand);
        if (lane == 0) swk[wid] = ((unsigned long long)wmax << 32) | (uint32_t)(~widx);
        __syncthreads();                       // bar 3
        if (wid == 0) {
            unsigned long long k = (lane < 16) ? swk[lane] : 0ull;
#pragma unroll
            for (int off = 8; off; off >>= 1) {
                unsigned long long ok = __shfl_xor_sync(0xffffffffu, k, off);
                if (ok > k) k = ok;
            }
            if (lane == 0) f = (int)(~(uint32_t)k & 0x1fffu);
        }
    }
}

// ---------------- grouping: one block per (b,c) ----------------
__global__ __launch_bounds__(256) void group_kernel(const float* __restrict__ coords,
                                                    const float* __restrict__ features,
                                                    const float* __restrict__ cent,
                                                    float* __restrict__ grouped) {
    const int bc = blockIdx.x;
    const int b = bc >> 10;
    const int tid = threadIdx.x;
    const float* cb = coords + (size_t)b * NPTS * 3;
    const float* fb = features + (size_t)b * NPTS * DFEAT;
    const float* x2b = g_x2 + b * NPTS;

    const float cx = cent[3 * bc], cy = cent[3 * bc + 1], cz = cent[3 * bc + 2];
    const float c2 = __fadd_rn(__fadd_rn(__fmul_rn(cx, cx), __fmul_rn(cy, cy)), __fmul_rn(cz, cz));
    const float r2 = 0.04f;

    __shared__ float sval[1024];
    __shared__ int sidx[1024];
    __shared__ int scnt;
    __shared__ unsigned long long swmin[8];
    __shared__ unsigned long long sbest;
    __shared__ int schosen[KNN];

    if (tid == 0) scnt = 0;
    __syncthreads();

    for (int n = tid; n < NPTS; n += 256) {
        float x = cb[3 * n], y = cb[3 * n + 1], z = cb[3 * n + 2];
        float dot = __fmaf_rn(cz, z, __fmaf_rn(cy, y, __fmul_rn(cx, x)));
        float d = __fadd_rn(__fmaf_rn(-2.0f, dot, c2), x2b[n]);
        if (d <= r2) {
            int p = atomicAdd(&scnt, 1);
            if (p < 1024) { sval[p] = d; sidx[p] = n; }
        }
    }
    __syncthreads();
    const int M = min(scnt, 1024);
    const int nsel = min(M, KNN);
    const int wid = tid >> 5, lane = tid & 31;

    for (int round = 0; round < nsel; round++) {
        unsigned long long bk = 0xFFFFFFFFFFFFFFFFull;
        for (int j = tid; j < M; j += 256) {
            unsigned u = __float_as_uint(sval[j]);
            u = (u & 0x80000000u) ? ~u : (u | 0x80000000u);
            unsigned long long k = ((unsigned long long)u << 32) | (unsigned)sidx[j];
            if (k < bk) bk = k;
        }
#pragma unroll
        for (int off = 16; off; off >>= 1) {
            unsigned long long ok = __shfl_down_sync(0xffffffffu, bk, off);
            if (ok < bk) bk = ok;
        }
        if (lane == 0) swmin[wid] = bk;
        __syncthreads();
        if (tid == 0) {
            unsigned long long m = swmin[0];
            for (int w = 1; w < 8; w++) if (swmin[w] < m) m = swmin[w];
            sbest = m;
        }
        __syncthreads();
        int n = (int)(unsigned)(sbest & 0xFFFFFFFFull);
        if (tid == 0) schosen[round] = n;
        for (int j = tid; j < M; j += 256)
            if (sidx[j] == n) sval[j] = f_inf();
        __syncthreads();
    }

    if (nsel < KNN && tid == 0) {
        int pos = nsel;
        for (int n = 0; n < NPTS && pos < KNN; n++) {
            float x = cb[3 * n], y = cb[3 * n + 1], z = cb[3 * n + 2];
            float dot = __fmaf_rn(cz, z, __fmaf_rn(cy, y, __fmul_rn(cx, x)));
            float d = __fadd_rn(__fmaf_rn(-2.0f, dot, c2), x2b[n]);
            if (!(d <= r2)) schosen[pos++] = n;
        }
    }
    __syncthreads();

    for (int t = tid; t < KNN * 16; t += 256) {
        int k = t >> 4, fc = t & 15;
        int n = schosen[k];
        float v;
        if (fc < 3) {
            float cen = (fc == 0) ? cx : ((fc == 1) ? cy : cz);
            v = cb[3 * n + fc] - cen;
        } else {
            v = fb[DFEAT * n + fc - 3];
        }
        grouped[((size_t)bc * KNN + k) * 16 + fc] = v;
    }
}

// ---------------- GEMM: register-tiled, k-major weights, float4 ----------------
// 256 threads; ROWS rows/block; thread = (rowg = tid>>3 handling RT rows, colg = tid&7
// handling VC = FOUT/8 cols). Per k: RT x-LDS + VC/4 LDS.128 -> 4-5 FMA/LDS.
template <int FIN, int FOUT, int ROWS, int SOFF, bool NORM>
__global__ __launch_bounds__(256) void gemm_kernel(const float* __restrict__ X,
                                                   const float* __restrict__ W,
                                                   const float* __restrict__ bias,
                                                   const float* __restrict__ gam,
                                                   const float* __restrict__ bet,
                                                   float* __restrict__ Y) {
    constexpr int VC = FOUT / 8;
    constexpr int RT = ROWS / 32;

    __shared__ float sW[FIN * FOUT];      // k-major: sW[k*FOUT + o]
    __shared__ float sB[FOUT];
    __shared__ float sA[FIN], sCc[FIN];
    __shared__ float sX[ROWS * FIN];

    const int tid = threadIdx.x;

    for (int i = tid; i < FIN * FOUT; i += 256) {
        int o = i / FIN, k = i % FIN;
        sW[k * FOUT + o] = W[i];
    }
    if (tid < FOUT) sB[tid] = bias[tid];
    if (NORM && tid < FIN) {
        double mu = g_stats[SOFF + tid] / (double)NROWS;
        double var = g_stats[SOFF + FIN + tid] / (double)NROWS - mu * mu;
        float a = (float)(1.0 / sqrt(var + 1e-5)) * gam[tid];
        sA[tid] = a;
        sCc[tid] = bet[tid] - (float)mu * a;
    }
    __syncthreads();

    const float4* xb4 = (const float4*)(X + (size_t)blockIdx.x * ROWS * FIN);
    for (int i = tid; i < ROWS * FIN / 4; i += 256) {
        float4 v = xb4[i];
        if (NORM) {
            int ch = (i * 4) % FIN;
            v.x = fmaxf(fmaf(v.x, sA[ch],     sCc[ch]),     0.0f);
            v.y = fmaxf(fmaf(v.y, sA[ch + 1], sCc[ch + 1]), 0.0f);
            v.z = fmaxf(fmaf(v.z, sA[ch + 2], sCc[ch + 2]), 0.0f);
            v.w = fmaxf(fmaf(v.w, sA[ch + 3], sCc[ch + 3]), 0.0f);
        }
        ((float4*)sX)[i] = v;
    }
    __syncthreads();

    const int colg = tid & 7, rowg = tid >> 3;
    const int r0 = rowg * RT;

    float acc[RT][VC];
#pragma unroll
    for (int t = 0; t < RT; t++)
#pragma unroll
        for (int j = 0; j < VC; j++) acc[t][j] = sB[colg * VC + j];

#pragma unroll
    for (int k = 0; k < FIN; k++) {
        float xv[RT];
#pragma unroll
        for (int t = 0; t < RT; t++) xv[t] = sX[(r0 + t) * FIN + k];
        const float4* wv = (const float4*)&sW[k * FOUT + colg * VC];
#pragma unroll
        for (int j4 = 0; j4 < VC / 4; j4++) {
            float4 w = wv[j4];
#pragma unroll
            for (int t = 0; t < RT; t++) {
                acc[t][j4 * 4 + 0] = fmaf(xv[t], w.x, acc[t][j4 * 4 + 0]);
                acc[t][j4 * 4 + 1] = fmaf(xv[t], w.y, acc[t][j4 * 4 + 1]);
                acc[t][j4 * 4 + 2] = fmaf(xv[t], w.z, acc[t][j4 * 4 + 2]);
                acc[t][j4 * 4 + 3] = fmaf(xv[t], w.w, acc[t][j4 * 4 + 3]);
            }
        }
    }
#pragma unroll
    for (int t = 0; t < RT; t++) {
        float* yr = Y + ((size_t)blockIdx.x * ROWS + r0 + t) * FOUT + colg * VC;
#pragma unroll
        for (int j4 = 0; j4 < VC / 4; j4++)
            ((float4*)yr)[j4] = make_float4(acc[t][j4 * 4], acc[t][j4 * 4 + 1],
                                            acc[t][j4 * 4 + 2], acc[t][j4 * 4 + 3]);
    }
}

// ---------------- per-channel sum / sumsq reduction ----------------
template <int F, int SOFF>
__global__ __launch_bounds__(256) void stats_kernel(const float* __restrict__ y) {
    constexpr int GROUPS = 256 / F;
    const int g = threadIdx.x / F, ch = threadIdx.x % F;
    const int base = blockIdx.x * 512;
    float s = 0.0f, ss = 0.0f;
    for (int r = base + g; r < base + 512; r += GROUPS) {
        float v = y[(size_t)r * F + ch];
        s += v;
        ss = fmaf(v, v, ss);
    }
    __shared__ float sh[256], sh2[256];
    sh[threadIdx.x] = s; sh2[threadIdx.x] = ss;
    __syncthreads();
    if (g == 0) {
#pragma unroll
        for (int gg = 1; gg < GROUPS; gg++) { s += sh[gg * F + ch]; ss += sh2[gg * F + ch]; }
        atomicAdd(&g_stats[SOFF + ch], (double)s);
        atomicAdd(&g_stats[SOFF + F + ch], (double)ss);
    }
}

// ---------------- BN+ReLU+maxpool over K ----------------
__global__ __launch_bounds__(128) void pool_kernel(const float* __restrict__ gam,
                                                   const float* __restrict__ bet,
                                                   float* __restrict__ out) {
    const int bc = blockIdx.x;
    const int o = threadIdx.x;
    double mu = g_stats[256 + o] / (double)NROWS;
    double var = g_stats[384 + o] / (double)NROWS - mu * mu;
    float a = (float)(1.0 / sqrt(var + 1e-5)) * gam[o];
    float c = bet[o] - (float)mu * a;
    float m = 0.0f;
#pragma unroll
    for (int k = 0; k < KNN; k++) {
        float v = g_y2[((size_t)bc * KNN + k) * 128 + o];
        v = fmaxf(fmaf(v, a, c), 0.0f);
        m = fmaxf(m, v);
    }
    out[CENT_FLOATS + (size_t)bc * 128 + o] = m;
}

extern "C" void kernel_launch(void* const* d_in, const int* in_sizes, int n_in,
                              void* d_out, int out_size) {
    // resolve inputs by element count (order-agnostic)
    int i_coords = -1, i_features = -1, i_w0 = -1, i_w1 = -1, i_w2 = -1;
    int idx64[6], n64 = 0;
    int idx128[3], n128 = 0;
    for (int i = 0; i < n_in; i++) {
        int s = in_sizes[i];
        if (s == 98304) i_coords = i;
        else if (s == 425984) i_features = i;
        else if (s == 1024) i_w0 = i;
        else if (s == 4096) i_w1 = i;
        else if (s == 8192) i_w2 = i;
        else if (s == 64 && n64 < 6) idx64[n64++] = i;
        else if (s == 128 && n128 < 3) idx128[n128++] = i;
    }

    int i_b0, i_g0, i_be0, i_b1, i_g1, i_be1, i_b2, i_g2, i_be2;
    if (i_coords == 0) {
        i_b0 = idx64[0]; i_g0 = idx64[1]; i_be0 = idx64[2];
        i_b1 = idx64[3]; i_g1 = idx64[4]; i_be1 = idx64[5];
        i_b2 = idx128[0]; i_g2 = idx128[1]; i_be2 = idx128[2];
    } else {
        i_b0 = idx64[0]; i_b1 = idx64[1]; i_be0 = idx64[2];
        i_be1 = idx64[3]; i_g0 = idx64[4]; i_g1 = idx64[5];
        i_b2 = idx128[0]; i_be2 = idx128[1]; i_g2 = idx128[2];
    }

    const float* coords   = (const float*)d_in[i_coords];
    const float* features = (const float*)d_in[i_features];
    const float* w0 = (const float*)d_in[i_w0];
    const float* b0 = (const float*)d_in[i_b0];
    const float* g0 = (const float*)d_in[i_g0];
    const float* be0 = (const float*)d_in[i_be0];
    const float* w1 = (const float*)d_in[i_w1];
    const float* b1 = (const float*)d_in[i_b1];
    const float* g1 = (const float*)d_in[i_g1];
    const float* be1 = (const float*)d_in[i_be1];
    const float* w2 = (const float*)d_in[i_w2];
    const float* b2 = (const float*)d_in[i_b2];
    const float* g2 = (const float*)d_in[i_g2];
    const float* be2 = (const float*)d_in[i_be2];
    float* out = (float*)d_out;

    (void)out_size;

    float* y0; float* y1; float* y2; float* gr;
    cudaGetSymbolAddress((void**)&gr, g_grouped);
    cudaGetSymbolAddress((void**)&y0, g_y0);
    cudaGetSymbolAddress((void**)&y1, g_y1);
    cudaGetSymbolAddress((void**)&y2, g_y2);

    zero_stats_kernel<<<1, 512>>>();
    fps_kernel<<<NB, 512>>>(coords, out);
    group_kernel<<<NB * NC, 256>>>(coords, features, out, gr);

    gemm_kernel<16, 64, 64, 0, false><<<NROWS / 64, 256>>>(gr, w0, b0, nullptr, nullptr, y0);
    stats_kernel<64, 0><<<256, 256>>>(y0);
    gemm_kernel<64, 64, 64, 0, true><<<NROWS / 64, 256>>>(y0, w1, b1, g0, be0, y1);
    stats_kernel<64, 128><<<256, 256>>>(y1);
    gemm_kernel<64, 128, 32, 128, true><<<NROWS / 32, 256>>>(y1, w2, b2, g1, be1, y2);
    stats_kernel<128, 256><<<256, 256>>>(y2);
    pool_kernel<<<NB * NC, 128>>>(g2, be2, out);
}

// round 8
// speedup vs baseline: 1.2805x; 1.0817x over previous
#include <cuda_runtime.h>
#include <cstdint>

#define NPTS   8192
#define NB     4
#define NC     1024
#define KNN    32
#define DFEAT  13
#define NROWS  (NB*NC*KNN)          // 131072
#define CENT_FLOATS (NB*NC*3)       // 12288

static __device__ float  g_x2[NB*NPTS];
static __device__ float  g_grouped[(size_t)NROWS*16];
static __device__ float  g_y0[(size_t)NROWS*64];
static __device__ float  g_y1[(size_t)NROWS*64];
static __device__ float  g_y2[(size_t)NROWS*128];
// stats: [0:64) s0 [64:128) ss0 [128:192) s1 [192:256) ss1 [256:384) s2 [384:512) ss2
static __device__ double g_stats[512];

__device__ __forceinline__ float f_inf() { return __int_as_float(0x7f800000); }

// packed f32x2 ops (per-lane IEEE rn, identical to scalar __fadd_rn/__fmul_rn)
#define MUL_F32X2(out, a, b) asm("mul.rn.f32x2 %0, %1, %2;" : "=l"(out) : "l"(a), "l"(b))
#define ADD_F32X2(out, a, b) asm("add.rn.f32x2 %0, %1, %2;" : "=l"(out) : "l"(a), "l"(b))
#define PACK_F32X2(out, lo, hi) asm("mov.b64 %0, {%1, %2};" : "=l"(out) : "r"(lo), "r"(hi))
#define UNPACK_F32X2(lo, hi, in) asm("mov.b64 {%0, %1}, %2;" : "=r"(lo), "=r"(hi) : "l"(in))

// ---------------- threefry2x32 (jax partitionable mode) ----------------
__device__ __forceinline__ uint32_t rotl32(uint32_t x, int d) { return (x << d) | (x >> (32 - d)); }

__device__ __forceinline__ void threefry2x32(uint32_t k0, uint32_t k1, uint32_t c0, uint32_t c1,
                                             uint32_t& o0, uint32_t& o1) {
    uint32_t ks0 = k0, ks1 = k1, ks2 = k0 ^ k1 ^ 0x1BD11BDAu;
    uint32_t x0 = c0 + ks0, x1 = c1 + ks1;
#define TF_R(r) { x0 += x1; x1 = rotl32(x1, r); x1 ^= x0; }
#define TF_A TF_R(13) TF_R(15) TF_R(26) TF_R(6)
#define TF_B TF_R(17) TF_R(29) TF_R(16) TF_R(24)
    TF_A; x0 += ks1; x1 += ks2 + 1u;
    TF_B; x0 += ks2; x1 += ks0 + 2u;
    TF_A; x0 += ks0; x1 += ks1 + 3u;
    TF_B; x0 += ks1; x1 += ks2 + 4u;
    TF_A; x0 += ks2; x1 += ks0 + 5u;
#undef TF_A
#undef TF_B
#undef TF_R
    o0 = x0; o1 = x1;
}

__global__ void zero_stats_kernel() {
    int i = threadIdx.x;
    if (i < 512) g_stats[i] = 0.0;
}

// ---------------- FPS: one block per batch, 512 threads x 16 points ----------------
// Packed-f32x2 d2 (bit-exact vs scalar rn / XLA). Argmax resolved in sqrt
// domain (jnp.linalg.norm + argmax, first-index ties). Warp-LOCAL sqrt
// threshold: any point whose sqrt equals the global max lies within 2 ulps of
// its own warp's d2 max, so warp_max-8ulp can never exclude a winner.
// 2 barriers/iteration; cross-warp reduce via 32-bit REDUX on split hi/lo.
__global__ __launch_bounds__(512, 1) void fps_kernel(const float* __restrict__ coords,
                                                     float* __restrict__ out_cent) {
    const int b = blockIdx.x;
    const float* cb = coords + (size_t)b * NPTS * 3;
    const int tid = threadIdx.x;
    const int wid = tid >> 5, lane = tid & 31;

    unsigned long long pxp[8], pyp[8], pzp[8];
    float dist[16];
#pragma unroll
    for (int t = 0; t < 16; t++) {
        int p = tid + t * 512;
        float x = cb[3 * p], y = cb[3 * p + 1], z = cb[3 * p + 2];
        dist[t] = f_inf();
        g_x2[b * NPTS + p] = __fadd_rn(__fadd_rn(__fmul_rn(x, x), __fmul_rn(y, y)),
                                       __fmul_rn(z, z));
    }
#pragma unroll
    for (int m = 0; m < 8; m++) {
        int p0 = tid + (2 * m) * 512, p1 = tid + (2 * m + 1) * 512;
        PACK_F32X2(pxp[m], __float_as_uint(cb[3 * p0]),     __float_as_uint(cb[3 * p1]));
        PACK_F32X2(pyp[m], __float_as_uint(cb[3 * p0 + 1]), __float_as_uint(cb[3 * p1 + 1]));
        PACK_F32X2(pzp[m], __float_as_uint(cb[3 * p0 + 2]), __float_as_uint(cb[3 * p1 + 2]));
    }

    __shared__ float scx, scy, scz;
    __shared__ uint32_t shi[16];   // per-warp max sqrt bits
    __shared__ uint32_t slo[16];   // per-warp min gidx at that max

    int f = 0;
    if (tid == 0) {
        // partitionable: k2 = threefry((0,42),(0,1)); bits_b = o0^o1 of threefry(k2,(0,b))
        uint32_t k2a, k2b, o0, o1;
        threefry2x32(0u, 42u, 0u, 1u, k2a, k2b);
        threefry2x32(k2a, k2b, 0u, (uint32_t)b, o0, o1);
        f = (int)((o0 ^ o1) & 8191u);
    }

    for (int it = 0; it < NC; ++it) {
        if (tid == 0) {
            float x = cb[3 * f], y = cb[3 * f + 1], z = cb[3 * f + 2];
            scx = x; scy = y; scz = z;
            float* oc = out_cent + ((size_t)b * NC + it) * 3;
            oc[0] = x; oc[1] = y; oc[2] = z;
        }
        __syncthreads();                       // bar A
        float fx = scx, fy = scy, fz = scz;
        unsigned long long nfx, nfy, nfz;
        {
            uint32_t nx = __float_as_uint(-fx), ny = __float_as_uint(-fy), nz = __float_as_uint(-fz);
            PACK_F32X2(nfx, nx, nx); PACK_F32X2(nfy, ny, ny); PACK_F32X2(nfz, nz, nz);
        }

        // Phase A: packed d2, min-update, thread-local max
        float mv = -1.0f;
#pragma unroll
        for (int m = 0; m < 8; m++) {
            unsigned long long dx, dy, dz, xx, yy, zz, s1, d2p;
            ADD_F32X2(dx, pxp[m], nfx);
            ADD_F32X2(dy, pyp[m], nfy);
            ADD_F32X2(dz, pzp[m], nfz);
            MUL_F32X2(xx, dx, dx);
            MUL_F32X2(yy, dy, dy);
            MUL_F32X2(zz, dz, dz);
            ADD_F32X2(s1, xx, yy);
            ADD_F32X2(d2p, s1, zz);
            uint32_t lo, hi;
            UNPACK_F32X2(lo, hi, d2p);
            float a = __uint_as_float(lo), c = __uint_as_float(hi);
            dist[2 * m]     = fminf(dist[2 * m], a);
            dist[2 * m + 1] = fminf(dist[2 * m + 1], c);
            mv = fmaxf(mv, dist[2 * m]);
            mv = fmaxf(mv, dist[2 * m + 1]);
        }
        // warp-local d2 max -> local sqrt threshold (d2 >= 0: bits monotone)
        uint32_t wmv = __reduce_max_sync(0xffffffffu, __float_as_uint(mv));
        uint32_t thr = (wmv >= 8u) ? (wmv - 8u) : 0u;

        // Phase B: sqrt only near-local-max candidates; (sqrt_bits, first-idx) winner
        uint32_t best = 0u; uint32_t bidx = 0x7fffffffu;
#pragma unroll
        for (int t = 0; t < 16; t++) {
            if (__float_as_uint(dist[t]) >= thr) {
                uint32_t sb = __float_as_uint(__fsqrt_rn(dist[t]));
                if (sb > best) { best = sb; bidx = (uint32_t)(tid + t * 512); }
            }
        }
        uint32_t wmax = __reduce_max_sync(0xffffffffu, best);
        uint32_t cand = (best == wmax) ? bidx : 0xffffffffu;
        uint32_t widx = __reduce_min_sync(0xffffffffu, cand);
        if (lane == 0) { shi[wid] = wmax; slo[wid] = widx; }
        __syncthreads();                       // bar B
        if (wid == 0) {
            uint32_t v = (lane < 16) ? shi[lane] : 0u;
            uint32_t m = __reduce_max_sync(0xffffffffu, v);
            uint32_t c = (v == m && lane < 16) ? slo[lane] : 0xffffffffu;
            uint32_t g = __reduce_min_sync(0xffffffffu, c);
            f = (int)(g & 0x1fffu);
        }
    }
}

// ---------------- grouping: one block per (b,c) ----------------
__global__ __launch_bounds__(256) void group_kernel(const float* __restrict__ coords,
                                                    const float* __restrict__ features,
                                                    const float* __restrict__ cent,
                                                    float* __restrict__ grouped) {
    const int bc = blockIdx.x;
    const int b = bc >> 10;
    const int tid = threadIdx.x;
    const int wid = tid >> 5, lane = tid & 31;
    const float* cb = coords + (size_t)b * NPTS * 3;
    const float* fb = features + (size_t)b * NPTS * DFEAT;
    const float* x2b = g_x2 + b * NPTS;

    const float cx = cent[3 * bc], cy = cent[3 * bc + 1], cz = cent[3 * bc + 2];
    const float c2 = __fadd_rn(__fadd_rn(__fmul_rn(cx, cx), __fmul_rn(cy, cy)), __fmul_rn(cz, cz));
    const float r2 = 0.04f;

    __shared__ float sval[1024];
    __shared__ int sidx[1024];
    __shared__ int scnt;
    __shared__ int schosen[KNN];

    if (tid == 0) scnt = 0;
    __syncthreads();

    for (int n = tid; n < NPTS; n += 256) {
        float x = cb[3 * n], y = cb[3 * n + 1], z = cb[3 * n + 2];
        float dot = __fmaf_rn(cz, z, __fmaf_rn(cy, y, __fmul_rn(cx, x)));
        float d = __fadd_rn(__fmaf_rn(-2.0f, dot, c2), x2b[n]);
        if (d <= r2) {
            int p = atomicAdd(&scnt, 1);
            if (p < 1024) { sval[p] = d; sidx[p] = n; }
        }
    }
    __syncthreads();
    const int M = min(scnt, 1024);
    const int nsel = min(M, KNN);

    // warp0-only selection: no block barriers inside the round loop
    if (wid == 0) {
        for (int round = 0; round < nsel; round++) {
            float bv = f_inf(); int bn = 0x7fffffff; int bj = -1;
            for (int j = lane; j < M; j += 32) {
                float v = sval[j]; int n = sidx[j];
                if (v < bv || (v == bv && n < bn)) { bv = v; bn = n; bj = j; }
            }
            uint32_t vb = __float_as_uint(bv);
            vb = (vb & 0x80000000u) ? ~vb : (vb | 0x80000000u);  // orderable
            uint32_t vmin = __reduce_min_sync(0xffffffffu, vb);
            uint32_t cand = (vb == vmin) ? (uint32_t)bn : 0xffffffffu;
            uint32_t nwin = __reduce_min_sync(0xffffffffu, cand);
            if (vb == vmin && (uint32_t)bn == nwin) sval[bj] = f_inf();
            if (lane == 0) schosen[round] = (int)nwin;
            __syncwarp();
        }
    }
    __syncthreads();

    if (nsel < KNN && tid == 0) {  // pad with lowest-index out-of-radius points (top_k on inf ties)
        int pos = nsel;
        for (int n = 0; n < NPTS && pos < KNN; n++) {
            float x = cb[3 * n], y = cb[3 * n + 1], z = cb[3 * n + 2];
            float dot = __fmaf_rn(cz, z, __fmaf_rn(cy, y, __fmul_rn(cx, x)));
            float d = __fadd_rn(__fmaf_rn(-2.0f, dot, c2), x2b[n]);
            if (!(d <= r2)) schosen[pos++] = n;
        }
    }
    __syncthreads();

    for (int t = tid; t < KNN * 16; t += 256) {
        int k = t >> 4, fc = t & 15;
        int n = schosen[k];
        float v;
        if (fc < 3) {
            float cen = (fc == 0) ? cx : ((fc == 1) ? cy : cz);
            v = cb[3 * n + fc] - cen;
        } else {
            v = fb[DFEAT * n + fc - 3];
        }
        grouped[((size_t)bc * KNN + k) * 16 + fc] = v;
    }
}

// ---------------- GEMM: register-tiled, k-major weights, float4 ----------------
template <int FIN, int FOUT, int ROWS, int SOFF, bool NORM>
__global__ __launch_bounds__(256) void gemm_kernel(const float* __restrict__ X,
                                                   const float* __restrict__ W,
                                                   const float* __restrict__ bias,
                                                   const float* __restrict__ gam,
                                                   const float* __restrict__ bet,
                                                   float* __restrict__ Y) {
    constexpr int VC = FOUT / 8;
    constexpr int RT = ROWS / 32;

    __shared__ float sW[FIN * FOUT];      // k-major: sW[k*FOUT + o]
    __shared__ float sB[FOUT];
    __shared__ float sA[FIN], sCc[FIN];
    __shared__ float sX[ROWS * FIN];

    const int tid = threadIdx.x;

    for (int i = tid; i < FIN * FOUT; i += 256) {
        int o = i / FIN, k = i % FIN;
        sW[k * FOUT + o] = W[i];
    }
    if (tid < FOUT) sB[tid] = bias[tid];
    if (NORM && tid < FIN) {
        double mu = g_stats[SOFF + tid] / (double)NROWS;
        double var = g_stats[SOFF + FIN + tid] / (double)NROWS - mu * mu;
        float a = (float)(1.0 / sqrt(var + 1e-5)) * gam[tid];
        sA[tid] = a;
        sCc[tid] = bet[tid] - (float)mu * a;
    }
    __syncthreads();

    const float4* xb4 = (const float4*)(X + (size_t)blockIdx.x * ROWS * FIN);
    for (int i = tid; i < ROWS * FIN / 4; i += 256) {
        float4 v = xb4[i];
        if (NORM) {
            int ch = (i * 4) % FIN;
            v.x = fmaxf(fmaf(v.x, sA[ch],     sCc[ch]),     0.0f);
            v.y = fmaxf(fmaf(v.y, sA[ch + 1], sCc[ch + 1]), 0.0f);
            v.z = fmaxf(fmaf(v.z, sA[ch + 2], sCc[ch + 2]), 0.0f);
            v.w = fmaxf(fmaf(v.w, sA[ch + 3], sCc[ch + 3]), 0.0f);
        }
        ((float4*)sX)[i] = v;
    }
    __syncthreads();

    const int colg = tid & 7, rowg = tid >> 3;
    const int r0 = rowg * RT;

    float acc[RT][VC];
#pragma unroll
    for (int t = 0; t < RT; t++)
#pragma unroll
        for (int j = 0; j < VC; j++) acc[t][j] = sB[colg * VC + j];

#pragma unroll
    for (int k = 0; k < FIN; k++) {
        float xv[RT];
#pragma unroll
        for (int t = 0; t < RT; t++) xv[t] = sX[(r0 + t) * FIN + k];
        const float4* wv = (const float4*)&sW[k * FOUT + colg * VC];
#pragma unroll
        for (int j4 = 0; j4 < VC / 4; j4++) {
            float4 w = wv[j4];
#pragma unroll
            for (int t = 0; t < RT; t++) {
                acc[t][j4 * 4 + 0] = fmaf(xv[t], w.x, acc[t][j4 * 4 + 0]);
                acc[t][j4 * 4 + 1] = fmaf(xv[t], w.y, acc[t][j4 * 4 + 1]);
                acc[t][j4 * 4 + 2] = fmaf(xv[t], w.z, acc[t][j4 * 4 + 2]);
                acc[t][j4 * 4 + 3] = fmaf(xv[t], w.w, acc[t][j4 * 4 + 3]);
            }
        }
    }
#pragma unroll
    for (int t = 0; t < RT; t++) {
        float* yr = Y + ((size_t)blockIdx.x * ROWS + r0 + t) * FOUT + colg * VC;
#pragma unroll
        for (int j4 = 0; j4 < VC / 4; j4++)
            ((float4*)yr)[j4] = make_float4(acc[t][j4 * 4], acc[t][j4 * 4 + 1],
                                            acc[t][j4 * 4 + 2], acc[t][j4 * 4 + 3]);
    }
}

// ---------------- per-channel sum / sumsq reduction ----------------
template <int F, int SOFF>
__global__ __launch_bounds__(256) void stats_kernel(const float* __restrict__ y) {
    constexpr int GROUPS = 256 / F;
    const int g = threadIdx.x / F, ch = threadIdx.x % F;
    const int base = blockIdx.x * 512;
    float s = 0.0f, ss = 0.0f;
    for (int r = base + g; r < base + 512; r += GROUPS) {
        float v = y[(size_t)r * F + ch];
        s += v;
        ss = fmaf(v, v, ss);
    }
    __shared__ float sh[256], sh2[256];
    sh[threadIdx.x] = s; sh2[threadIdx.x] = ss;
    __syncthreads();
    if (g == 0) {
#pragma unroll
        for (int gg = 1; gg < GROUPS; gg++) { s += sh[gg * F + ch]; ss += sh2[gg * F + ch]; }
        atomicAdd(&g_stats[SOFF + ch], (double)s);
        atomicAdd(&g_stats[SOFF + F + ch], (double)ss);
    }
}

// ---------------- BN+ReLU+maxpool over K ----------------
__global__ __launch_bounds__(128) void pool_kernel(const float* __restrict__ gam,
                                                   const float* __restrict__ bet,
                                                   float* __restrict__ out) {
    const int bc = blockIdx.x;
    const int o = threadIdx.x;
    double mu = g_stats[256 + o] / (double)NROWS;
    double var = g_stats[384 + o] / (double)NROWS - mu * mu;
    float a = (float)(1.0 / sqrt(var + 1e-5)) * gam[o];
    float c = bet[o] - (float)mu * a;
    float m = 0.0f;
#pragma unroll
    for (int k = 0; k < KNN; k++) {
        float v = g_y2[((size_t)bc * KNN + k) * 128 + o];
        v = fmaxf(fmaf(v, a, c), 0.0f);
        m = fmaxf(m, v);
    }
    out[CENT_FLOATS + (size_t)bc * 128 + o] = m;
}

extern "C" void kernel_launch(void* const* d_in, const int* in_sizes, int n_in,
                              void* d_out, int out_size) {
    // resolve inputs by element count (order-agnostic)
    int i_coords = -1, i_features = -1, i_w0 = -1, i_w1 = -1, i_w2 = -1;
    int idx64[6], n64 = 0;
    int idx128[3], n128 = 0;
    for (int i = 0; i < n_in; i++) {
        int s = in_sizes[i];
        if (s == 98304) i_coords = i;
        else if (s == 425984) i_features = i;
        else if (s == 1024) i_w0 = i;
        else if (s == 4096) i_w1 = i;
        else if (s == 8192) i_w2 = i;
        else if (s == 64 && n64 < 6) idx64[n64++] = i;
        else if (s == 128 && n128 < 3) idx128[n128++] = i;
    }

    int i_b0, i_g0, i_be0, i_b1, i_g1, i_be1, i_b2, i_g2, i_be2;
    if (i_coords == 0) {
        i_b0 = idx64[0]; i_g0 = idx64[1]; i_be0 = idx64[2];
        i_b1 = idx64[3]; i_g1 = idx64[4]; i_be1 = idx64[5];
        i_b2 = idx128[0]; i_g2 = idx128[1]; i_be2 = idx128[2];
    } else {
        i_b0 = idx64[0]; i_b1 = idx64[1]; i_be0 = idx64[2];
        i_be1 = idx64[3]; i_g0 = idx64[4]; i_g1 = idx64[5];
        i_b2 = idx128[0]; i_be2 = idx128[1]; i_g2 = idx128[2];
    }

    const float* coords   = (const float*)d_in[i_coords];
    const float* features = (const float*)d_in[i_features];
    const float* w0 = (const float*)d_in[i_w0];
    const float* b0 = (const float*)d_in[i_b0];
    const float* g0 = (const float*)d_in[i_g0];
    const float* be0 = (const float*)d_in[i_be0];
    const float* w1 = (const float*)d_in[i_w1];
    const float* b1 = (const float*)d_in[i_b1];
    const float* g1 = (const float*)d_in[i_g1];
    const float* be1 = (const float*)d_in[i_be1];
    const float* w2 = (const float*)d_in[i_w2];
    const float* b2 = (const float*)d_in[i_b2];
    const float* g2 = (const float*)d_in[i_g2];
    const float* be2 = (const float*)d_in[i_be2];
    float* out = (float*)d_out;

    (void)out_size;

    float* y0; float* y1; float* y2; float* gr;
    cudaGetSymbolAddress((void**)&gr, g_grouped);
    cudaGetSymbolAddress((void**)&y0, g_y0);
    cudaGetSymbolAddress((void**)&y1, g_y1);
    cudaGetSymbolAddress((void**)&y2, g_y2);

    zero_stats_kernel<<<1, 512>>>();
    fps_kernel<<<NB, 512>>>(coords, out);
    group_kernel<<<NB * NC, 256>>>(coords, features, out, gr);

    gemm_kernel<16, 64, 64, 0, false><<<NROWS / 64, 256>>>(gr, w0, b0, nullptr, nullptr, y0);
    stats_kernel<64, 0><<<256, 256>>>(y0);
    gemm_kernel<64, 64, 64, 0, true><<<NROWS / 64, 256>>>(y0, w1, b1, g0, be0, y1);
    stats_kernel<64, 128><<<256, 256>>>(y1);
    gemm_kernel<64, 128, 32, 128, true><<<NROWS / 32, 256>>>(y1, w2, b2, g1, be1, y2);
    stats_kernel<128, 256><<<256, 256>>>(y2);
    pool_kernel<<<NB * NC, 128>>>(g2, be2, out);
}

// round 10
// speedup vs baseline: 1.3312x; 1.0396x over previous
#include <cuda_runtime.h>
#include <cstdint>

#define NPTS   8192
#define NB     4
#define NC     1024
#define KNN    32
#define DFEAT  13
#define NROWS  (NB*NC*KNN)          // 131072
#define CENT_FLOATS (NB*NC*3)       // 12288

static __device__ float  g_x2[NB*NPTS];
static __device__ float  g_grouped[(size_t)NROWS*16];
static __device__ float  g_y0[(size_t)NROWS*64];
static __device__ float  g_y1[(size_t)NROWS*64];
static __device__ float  g_y2[(size_t)NROWS*128];
// stats: [0:64) s0 [64:128) ss0 [128:192) s1 [192:256) ss1 [256:384) s2 [384:512) ss2
static __device__ double g_stats[512];

__device__ __forceinline__ float f_inf() { return __int_as_float(0x7f800000); }

// packed f32x2 ops (per-lane IEEE rn, identical to scalar __fadd_rn/__fmul_rn).
// NOTE: only add/mul/fma exist in the f32x2 family on sm_100 — no min/max.
#define MUL_F32X2(out, a, b) asm("mul.rn.f32x2 %0, %1, %2;" : "=l"(out) : "l"(a), "l"(b))
#define ADD_F32X2(out, a, b) asm("add.rn.f32x2 %0, %1, %2;" : "=l"(out) : "l"(a), "l"(b))
#define PACK_F32X2(out, lo, hi) asm("mov.b64 %0, {%1, %2};" : "=l"(out) : "r"(lo), "r"(hi))
#define UNPACK_F32X2(lo, hi, in) asm("mov.b64 {%0, %1}, %2;" : "=r"(lo), "=r"(hi) : "l"(in))

// ---------------- threefry2x32 (jax partitionable mode) ----------------
__device__ __forceinline__ uint32_t rotl32(uint32_t x, int d) { return (x << d) | (x >> (32 - d)); }

__device__ __forceinline__ void threefry2x32(uint32_t k0, uint32_t k1, uint32_t c0, uint32_t c1,
                                             uint32_t& o0, uint32_t& o1) {
    uint32_t ks0 = k0, ks1 = k1, ks2 = k0 ^ k1 ^ 0x1BD11BDAu;
    uint32_t x0 = c0 + ks0, x1 = c1 + ks1;
#define TF_R(r) { x0 += x1; x1 = rotl32(x1, r); x1 ^= x0; }
#define TF_A TF_R(13) TF_R(15) TF_R(26) TF_R(6)
#define TF_B TF_R(17) TF_R(29) TF_R(16) TF_R(24)
    TF_A; x0 += ks1; x1 += ks2 + 1u;
    TF_B; x0 += ks2; x1 += ks0 + 2u;
    TF_A; x0 += ks0; x1 += ks1 + 3u;
    TF_B; x0 += ks1; x1 += ks2 + 4u;
    TF_A; x0 += ks2; x1 += ks0 + 5u;
#undef TF_A
#undef TF_B
#undef TF_R
    o0 = x0; o1 = x1;
}

__global__ void zero_stats_kernel() {
    int i = threadIdx.x;
    if (i < 512) g_stats[i] = 0.0;
}

// ---------------- FPS: one block per batch, 512 threads x 16 points ----------------
// Packed-f32x2 d2 (bit-exact vs scalar rn / XLA); scalar min/max updates.
// Argmax in sqrt domain (jnp.linalg.norm + argmax, first-index ties);
// warp-local sqrt threshold (warp_max - 8 ulp can never exclude the winner).
// SINGLE barrier per iteration: per-warp (max,idx) in double-buffered smem,
// every warp redundantly reduces them; centroid via same-address LDG broadcast.
__global__ __launch_bounds__(512, 1) void fps_kernel(const float* __restrict__ coords,
                                                     float* __restrict__ out_cent) {
    const int b = blockIdx.x;
    const float* cb = coords + (size_t)b * NPTS * 3;
    const int tid = threadIdx.x;
    const int wid = tid >> 5, lane = tid & 31;

    unsigned long long pxp[8], pyp[8], pzp[8];
    float dist[16];
#pragma unroll
    for (int t = 0; t < 16; t++) {
        int p = tid + t * 512;
        float x = cb[3 * p], y = cb[3 * p + 1], z = cb[3 * p + 2];
        dist[t] = f_inf();
        g_x2[b * NPTS + p] = __fadd_rn(__fadd_rn(__fmul_rn(x, x), __fmul_rn(y, y)),
                                       __fmul_rn(z, z));
    }
#pragma unroll
    for (int m = 0; m < 8; m++) {
        int p0 = tid + (2 * m) * 512, p1 = tid + (2 * m + 1) * 512;
        PACK_F32X2(pxp[m], __float_as_uint(cb[3 * p0]),     __float_as_uint(cb[3 * p1]));
        PACK_F32X2(pyp[m], __float_as_uint(cb[3 * p0 + 1]), __float_as_uint(cb[3 * p1 + 1]));
        PACK_F32X2(pzp[m], __float_as_uint(cb[3 * p0 + 2]), __float_as_uint(cb[3 * p1 + 2]));
    }

    __shared__ uint32_t shi[2][16];   // per-warp max sqrt bits (double-buffered)
    __shared__ uint32_t slo[2][16];   // per-warp min gidx at that max

    // all threads compute far0 (partitionable threefry; cheap, once)
    int f;
    {
        uint32_t k2a, k2b, o0, o1;
        threefry2x32(0u, 42u, 0u, 1u, k2a, k2b);
        threefry2x32(k2a, k2b, 0u, (uint32_t)b, o0, o1);
        f = (int)((o0 ^ o1) & 8191u);
    }

    for (int it = 0; it < NC; ++it) {
        const int buf = it & 1;
        float fx = cb[3 * f], fy = cb[3 * f + 1], fz = cb[3 * f + 2];  // L1 broadcast
        if (tid == 0) {
            float* oc = out_cent + ((size_t)b * NC + it) * 3;
            oc[0] = fx; oc[1] = fy; oc[2] = fz;
        }
        unsigned long long nfx, nfy, nfz;
        {
            uint32_t nx = __float_as_uint(-fx), ny = __float_as_uint(-fy), nz = __float_as_uint(-fz);
            PACK_F32X2(nfx, nx, nx); PACK_F32X2(nfy, ny, ny); PACK_F32X2(nfz, nz, nz);
        }

        // Phase A: packed d2, scalar min-update + running max
        float mv = -1.0f;
#pragma unroll
        for (int m = 0; m < 8; m++) {
            unsigned long long dx, dy, dz, xx, yy, zz, s1, d2p;
            ADD_F32X2(dx, pxp[m], nfx);
            ADD_F32X2(dy, pyp[m], nfy);
            ADD_F32X2(dz, pzp[m], nfz);
            MUL_F32X2(xx, dx, dx);
            MUL_F32X2(yy, dy, dy);
            MUL_F32X2(zz, dz, dz);
            ADD_F32X2(s1, xx, yy);
            ADD_F32X2(d2p, s1, zz);
            uint32_t lo, hi;
            UNPACK_F32X2(lo, hi, d2p);
            float a = __uint_as_float(lo), c = __uint_as_float(hi);
            dist[2 * m]     = fminf(dist[2 * m], a);
            dist[2 * m + 1] = fminf(dist[2 * m + 1], c);
            mv = fmaxf(mv, dist[2 * m]);
            mv = fmaxf(mv, dist[2 * m + 1]);
        }
        // warp-local d2 max -> local sqrt threshold (d2 >= 0: bits monotone)
        uint32_t wmv = __reduce_max_sync(0xffffffffu, __float_as_uint(mv));
        uint32_t thr = (wmv >= 8u) ? (wmv - 8u) : 0u;
        float thr_f = __uint_as_float(thr);

        // Phase B: sqrt only near-warp-max candidates; (sqrt_bits, first-idx) winner
        uint32_t best = 0u; uint32_t bidx = 0x7fffffffu;
#pragma unroll
        for (int t = 0; t < 16; t++) {
            if (dist[t] >= thr_f) {
                uint32_t sb = __float_as_uint(__fsqrt_rn(dist[t]));
                if (sb > best) { best = sb; bidx = (uint32_t)(tid + t * 512); }
            }
        }
        uint32_t wmax = __reduce_max_sync(0xffffffffu, best);
        uint32_t cand = (best == wmax) ? bidx : 0xffffffffu;
        uint32_t widx = __reduce_min_sync(0xffffffffu, cand);
        if (lane == 0) { shi[buf][wid] = wmax; slo[buf][wid] = widx; }
        __syncthreads();                       // the only barrier per iteration
        // every warp reduces the 16 per-warp results
        uint32_t v = (lane < 16) ? shi[buf][lane] : 0u;
        uint32_t m = __reduce_max_sync(0xffffffffu, v);
        uint32_t c = (v == m && lane < 16) ? slo[buf][lane] : 0xffffffffu;
        uint32_t g = __reduce_min_sync(0xffffffffu, c);
        f = (int)(g & 0x1fffu);
    }
}

// ---------------- grouping: one block per (b,c) ----------------
__global__ __launch_bounds__(256) void group_kernel(const float* __restrict__ coords,
                                                    const float* __restrict__ features,
                                                    const float* __restrict__ cent,
                                                    float* __restrict__ grouped) {
    const int bc = blockIdx.x;
    const int b = bc >> 10;
    const int tid = threadIdx.x;
    const int wid = tid >> 5, lane = tid & 31;
    const float* cb = coords + (size_t)b * NPTS * 3;
    const float* fb = features + (size_t)b * NPTS * DFEAT;
    const float* x2b = g_x2 + b * NPTS;

    const float cx = cent[3 * bc], cy = cent[3 * bc + 1], cz = cent[3 * bc + 2];
    const float c2 = __fadd_rn(__fadd_rn(__fmul_rn(cx, cx), __fmul_rn(cy, cy)), __fmul_rn(cz, cz));
    const float r2 = 0.04f;

    __shared__ float sval[1024];
    __shared__ int sidx[1024];
    __shared__ int scnt;
    __shared__ int schosen[KNN];

    if (tid == 0) scnt = 0;
    __syncthreads();

    for (int n = tid; n < NPTS; n += 256) {
        float x = cb[3 * n], y = cb[3 * n + 1], z = cb[3 * n + 2];
        float dot = __fmaf_rn(cz, z, __fmaf_rn(cy, y, __fmul_rn(cx, x)));
        float d = __fadd_rn(__fmaf_rn(-2.0f, dot, c2), x2b[n]);
        if (d <= r2) {
            int p = atomicAdd(&scnt, 1);
            if (p < 1024) { sval[p] = d; sidx[p] = n; }
        }
    }
    __syncthreads();
    const int M = min(scnt, 1024);
    const int nsel = min(M, KNN);

    // warp0-only selection: no block barriers inside the round loop
    if (wid == 0) {
        for (int round = 0; round < nsel; round++) {
            float bv = f_inf(); int bn = 0x7fffffff; int bj = -1;
            for (int j = lane; j < M; j += 32) {
                float v = sval[j]; int n = sidx[j];
                if (v < bv || (v == bv && n < bn)) { bv = v; bn = n; bj = j; }
            }
            uint32_t vb = __float_as_uint(bv);
            vb = (vb & 0x80000000u) ? ~vb : (vb | 0x80000000u);  // orderable
            uint32_t vmin = __reduce_min_sync(0xffffffffu, vb);
            uint32_t cand = (vb == vmin) ? (uint32_t)bn : 0xffffffffu;
            uint32_t nwin = __reduce_min_sync(0xffffffffu, cand);
            if (vb == vmin && (uint32_t)bn == nwin) sval[bj] = f_inf();
            if (lane == 0) schosen[round] = (int)nwin;
            __syncwarp();
        }
    }
    __syncthreads();

    if (nsel < KNN && tid == 0) {  // pad with lowest-index out-of-radius points (top_k on inf ties)
        int pos = nsel;
        for (int n = 0; n < NPTS && pos < KNN; n++) {
            float x = cb[3 * n], y = cb[3 * n + 1], z = cb[3 * n + 2];
            float dot = __fmaf_rn(cz, z, __fmaf_rn(cy, y, __fmul_rn(cx, x)));
            float d = __fadd_rn(__fmaf_rn(-2.0f, dot, c2), x2b[n]);
            if (!(d <= r2)) schosen[pos++] = n;
        }
    }
    __syncthreads();

    for (int t = tid; t < KNN * 16; t += 256) {
        int k = t >> 4, fc = t & 15;
        int n = schosen[k];
        float v;
        if (fc < 3) {
            float cen = (fc == 0) ? cx : ((fc == 1) ? cy : cz);
            v = cb[3 * n + fc] - cen;
        } else {
            v = fb[DFEAT * n + fc - 3];
        }
        grouped[((size_t)bc * KNN + k) * 16 + fc] = v;
    }
}

// ---------------- GEMM: register-tiled, k-major weights, float4 ----------------
template <int FIN, int FOUT, int ROWS, int SOFF, bool NORM>
__global__ __launch_bounds__(256) void gemm_kernel(const float* __restrict__ X,
                                                   const float* __restrict__ W,
                                                   const float* __restrict__ bias,
                                                   const float* __restrict__ gam,
                                                   const float* __restrict__ bet,
                                                   float* __restrict__ Y) {
    constexpr int VC = FOUT / 8;
    constexpr int RT = ROWS / 32;

    __shared__ float sW[FIN * FOUT];      // k-major: sW[k*FOUT + o]
    __shared__ float sB[FOUT];
    __shared__ float sA[FIN], sCc[FIN];
    __shared__ float sX[ROWS * FIN];

    const int tid = threadIdx.x;

    for (int i = tid; i < FIN * FOUT; i += 256) {
        int o = i / FIN, k = i % FIN;
        sW[k * FOUT + o] = W[i];
    }
    if (tid < FOUT) sB[tid] = bias[tid];
    if (NORM && tid < FIN) {
        double mu = g_stats[SOFF + tid] / (double)NROWS;
        double var = g_stats[SOFF + FIN + tid] / (double)NROWS - mu * mu;
        float a = (float)(1.0 / sqrt(var + 1e-5)) * gam[tid];
        sA[tid] = a;
        sCc[tid] = bet[tid] - (float)mu * a;
    }
    __syncthreads();

    const float4* xb4 = (const float4*)(X + (size_t)blockIdx.x * ROWS * FIN);
    for (int i = tid; i < ROWS * FIN / 4; i += 256) {
        float4 v = xb4[i];
        if (NORM) {
            int ch = (i * 4) % FIN;
            v.x = fmaxf(fmaf(v.x, sA[ch],     sCc[ch]),     0.0f);
            v.y = fmaxf(fmaf(v.y, sA[ch + 1], sCc[ch + 1]), 0.0f);
            v.z = fmaxf(fmaf(v.z, sA[ch + 2], sCc[ch + 2]), 0.0f);
            v.w = fmaxf(fmaf(v.w, sA[ch + 3], sCc[ch + 3]), 0.0f);
        }
        ((float4*)sX)[i] = v;
    }
    __syncthreads();

    const int colg = tid & 7, rowg = tid >> 3;
    const int r0 = rowg * RT;

    float acc[RT][VC];
#pragma unroll
    for (int t = 0; t < RT; t++)
#pragma unroll
        for (int j = 0; j < VC; j++) acc[t][j] = sB[colg * VC + j];

#pragma unroll
    for (int k = 0; k < FIN; k++) {
        float xv[RT];
#pragma unroll
        for (int t = 0; t < RT; t++) xv[t] = sX[(r0 + t) * FIN + k];
        const float4* wv = (const float4*)&sW[k * FOUT + colg * VC];
#pragma unroll
        for (int j4 = 0; j4 < VC / 4; j4++) {
            float4 w = wv[j4];
#pragma unroll
            for (int t = 0; t < RT; t++) {
                acc[t][j4 * 4 + 0] = fmaf(xv[t], w.x, acc[t][j4 * 4 + 0]);
                acc[t][j4 * 4 + 1] = fmaf(xv[t], w.y, acc[t][j4 * 4 + 1]);
                acc[t][j4 * 4 + 2] = fmaf(xv[t], w.z, acc[t][j4 * 4 + 2]);
                acc[t][j4 * 4 + 3] = fmaf(xv[t], w.w, acc[t][j4 * 4 + 3]);
            }
        }
    }
#pragma unroll
    for (int t = 0; t < RT; t++) {
        float* yr = Y + ((size_t)blockIdx.x * ROWS + r0 + t) * FOUT + colg * VC;
#pragma unroll
        for (int j4 = 0; j4 < VC / 4; j4++)
            ((float4*)yr)[j4] = make_float4(acc[t][j4 * 4], acc[t][j4 * 4 + 1],
                                            acc[t][j4 * 4 + 2], acc[t][j4 * 4 + 3]);
    }
}

// ---------------- per-channel sum / sumsq reduction ----------------
template <int F, int SOFF>
__global__ __launch_bounds__(256) void stats_kernel(const float* __restrict__ y) {
    constexpr int GROUPS = 256 / F;
    const int g = threadIdx.x / F, ch = threadIdx.x % F;
    const int base = blockIdx.x * 512;
    float s = 0.0f, ss = 0.0f;
    for (int r = base + g; r < base + 512; r += GROUPS) {
        float v = y[(size_t)r * F + ch];
        s += v;
        ss = fmaf(v, v, ss);
    }
    __shared__ float sh[256], sh2[256];
    sh[threadIdx.x] = s; sh2[threadIdx.x] = ss;
    __syncthreads();
    if (g == 0) {
#pragma unroll
        for (int gg = 1; gg < GROUPS; gg++) { s += sh[gg * F + ch]; ss += sh2[gg * F + ch]; }
        atomicAdd(&g_stats[SOFF + ch], (double)s);
        atomicAdd(&g_stats[SOFF + F + ch], (double)ss);
    }
}

// ---------------- BN+ReLU+maxpool over K ----------------
__global__ __launch_bounds__(128) void pool_kernel(const float* __restrict__ gam,
                                                   const float* __restrict__ bet,
                                                   float* __restrict__ out) {
    const int bc = blockIdx.x;
    const int o = threadIdx.x;
    double mu = g_stats[256 + o] / (double)NROWS;
    double var = g_stats[384 + o] / (double)NROWS - mu * mu;
    float a = (float)(1.0 / sqrt(var + 1e-5)) * gam[o];
    float c = bet[o] - (float)mu * a;
    float m = 0.0f;
#pragma unroll
    for (int k = 0; k < KNN; k++) {
        float v = g_y2[((size_t)bc * KNN + k) * 128 + o];
        v = fmaxf(fmaf(v, a, c), 0.0f);
        m = fmaxf(m, v);
    }
    out[CENT_FLOATS + (size_t)bc * 128 + o] = m;
}

extern "C" void kernel_launch(void* const* d_in, const int* in_sizes, int n_in,
                              void* d_out, int out_size) {
    // resolve inputs by element count (order-agnostic)
    int i_coords = -1, i_features = -1, i_w0 = -1, i_w1 = -1, i_w2 = -1;
    int idx64[6], n64 = 0;
    int idx128[3], n128 = 0;
    for (int i = 0; i < n_in; i++) {
        int s = in_sizes[i];
        if (s == 98304) i_coords = i;
        else if (s == 425984) i_features = i;
        else if (s == 1024) i_w0 = i;
        else if (s == 4096) i_w1 = i;
        else if (s == 8192) i_w2 = i;
        else if (s == 64 && n64 < 6) idx64[n64++] = i;
        else if (s == 128 && n128 < 3) idx128[n128++] = i;
    }

    int i_b0, i_g0, i_be0, i_b1, i_g1, i_be1, i_b2, i_g2, i_be2;
    if (i_coords == 0) {
        i_b0 = idx64[0]; i_g0 = idx64[1]; i_be0 = idx64[2];
        i_b1 = idx64[3]; i_g1 = idx64[4]; i_be1 = idx64[5];
        i_b2 = idx128[0]; i_g2 = idx128[1]; i_be2 = idx128[2];
    } else {
        i_b0 = idx64[0]; i_b1 = idx64[1]; i_be0 = idx64[2];
        i_be1 = idx64[3]; i_g0 = idx64[4]; i_g1 = idx64[5];
        i_b2 = idx128[0]; i_be2 = idx128[1]; i_g2 = idx128[2];
    }

    const float* coords   = (const float*)d_in[i_coords];
    const float* features = (const float*)d_in[i_features];
    const float* w0 = (const float*)d_in[i_w0];
    const float* b0 = (const float*)d_in[i_b0];
    const float* g0 = (const float*)d_in[i_g0];
    const float* be0 = (const float*)d_in[i_be0];
    const float* w1 = (const float*)d_in[i_w1];
    const float* b1 = (const float*)d_in[i_b1];
    const float* g1 = (const float*)d_in[i_g1];
    const float* be1 = (const float*)d_in[i_be1];
    const float* w2 = (const float*)d_in[i_w2];
    const float* b2 = (const float*)d_in[i_b2];
    const float* g2 = (const float*)d_in[i_g2];
    const float* be2 = (const float*)d_in[i_be2];
    float* out = (float*)d_out;

    (void)out_size;

    float* y0; float* y1; float* y2; float* gr;
    cudaGetSymbolAddress((void**)&gr, g_grouped);
    cudaGetSymbolAddress((void**)&y0, g_y0);
    cudaGetSymbolAddress((void**)&y1, g_y1);
    cudaGetSymbolAddress((void**)&y2, g_y2);

    zero_stats_kernel<<<1, 512>>>();
    fps_kernel<<<NB, 512>>>(coords, out);
    group_kernel<<<NB * NC, 256>>>(coords, features, out, gr);

    gemm_kernel<16, 64, 64, 0, false><<<NROWS / 64, 256>>>(gr, w0, b0, nullptr, nullptr, y0);
    stats_kernel<64, 0><<<256, 256>>>(y0);
    gemm_kernel<64, 64, 64, 0, true><<<NROWS / 64, 256>>>(y0, w1, b1, g0, be0, y1);
    stats_kernel<64, 128><<<256, 256>>>(y1);
    gemm_kernel<64, 128, 32, 128, true><<<NROWS / 32, 256>>>(y1, w2, b2, g1, be1, y2);
    stats_kernel<128, 256><<<256, 256>>>(y2);
    pool_kernel<<<NB * NC, 128>>>(g2, be2, out);
}